// round 1
// baseline (speedup 1.0000x reference)
#include <cuda_runtime.h>
#include <cuda_bf16.h>
#include <math.h>

#define BS    12288     // 3 * 4096
#define BATCH 4096
#define D     256
#define TINV  10.0f     // 1 / temp
#define TILE  64
#define KC    32
#define NB    (BS / TILE)   // 192

// Scratch (device globals; no allocation allowed)
__device__ float g_xn[BS * D];     // normalized rows
__device__ float g_den[BS];        // masked row sums of exp
__device__ float g_num[3 * BATCH]; // n12, n13, n23

// ---------------------------------------------------------------------------
// Kernel 1: row-normalize (cosine prep) + zero g_den
// grid = BS blocks, 256 threads (one element each)
// ---------------------------------------------------------------------------
__global__ __launch_bounds__(256) void k_normalize(const float* __restrict__ x) {
    const int row = blockIdx.x;
    const int tid = threadIdx.x;
    __shared__ float red[8];

    float v = x[row * D + tid];
    float ss = v * v;
    // warp reduce
    #pragma unroll
    for (int s = 16; s >= 1; s >>= 1) ss += __shfl_xor_sync(0xffffffffu, ss, s);
    if ((tid & 31) == 0) red[tid >> 5] = ss;
    __syncthreads();
    if (tid < 32) {
        float t = (tid < 8) ? red[tid] : 0.0f;
        #pragma unroll
        for (int s = 4; s >= 1; s >>= 1) t += __shfl_xor_sync(0xffffffffu, t, s);
        if (tid == 0) red[0] = t;
    }
    __syncthreads();
    const float nrm = sqrtf(red[0]);
    const float inv = 1.0f / fmaxf(nrm, 1e-6f);
    g_xn[row * D + tid] = v * inv;
    if (tid == 0) g_den[row] = 0.0f;
}

// ---------------------------------------------------------------------------
// Kernel 2: the three numerator dot products per p
// grid = BATCH blocks, 96 threads (3 warps: pair 0=(p,B+p), 1=(p,2B+p), 2=(B+p,2B+p))
// ---------------------------------------------------------------------------
__global__ __launch_bounds__(96) void k_numerators() {
    const int p    = blockIdx.x;
    const int w    = threadIdx.x >> 5;   // 0..2
    const int lane = threadIdx.x & 31;

    int ra, rb;
    if (w == 0)      { ra = p;         rb = BATCH + p;     }
    else if (w == 1) { ra = p;         rb = 2 * BATCH + p; }
    else             { ra = BATCH + p; rb = 2 * BATCH + p; }

    const float* a = g_xn + ra * D;
    const float* b = g_xn + rb * D;
    float dot = 0.0f;
    #pragma unroll
    for (int u = 0; u < D / 32; ++u) {
        int idx = lane + 32 * u;
        dot = fmaf(a[idx], b[idx], dot);
    }
    #pragma unroll
    for (int s = 16; s >= 1; s >>= 1) dot += __shfl_xor_sync(0xffffffffu, dot, s);
    if (lane == 0) g_num[w * BATCH + p] = expf(dot * TINV);
}

// ---------------------------------------------------------------------------
// Kernel 3: symmetric masked-rowsum GEMM.
// Upper-triangular 64x64 tiles only (bj >= bi). Each block computes the
// 64x64 exp tile; accumulates masked row sums into den[i-rows] and (for
// off-diagonal tiles) masked column sums into den[j-rows].
// Residue trick: i0,j0,cy*4,cx*4 are all multiples of 4, so the mask
// (col%4 == row%4) is exactly micro-tile (i==j).
// 256 threads: cx = tid&15 (cols), cy = tid>>4 (rows), 4x4 per thread.
// ---------------------------------------------------------------------------
__global__ __launch_bounds__(256) void k_den_gemm() {
    const int bi = blockIdx.y;
    const int bj = blockIdx.x;
    if (bj < bi) return;

    __shared__ float As[KC][TILE + 1];
    __shared__ float Bs[KC][TILE + 1];
    __shared__ float colred[TILE];

    const int tid = threadIdx.x;
    const int cx = tid & 15;
    const int cy = tid >> 4;
    const int i0 = bi * TILE;
    const int j0 = bj * TILE;

    if (tid < TILE) colred[tid] = 0.0f;

    float acc[4][4];
    #pragma unroll
    for (int i = 0; i < 4; ++i)
        #pragma unroll
        for (int j = 0; j < 4; ++j) acc[i][j] = 0.0f;

    for (int kc = 0; kc < D; kc += KC) {
        __syncthreads();
        // stage 64 rows x 32 k for A and B (2048 floats each, 8 per thread)
        #pragma unroll
        for (int t = 0; t < 8; ++t) {
            int idx = tid + t * 256;
            int r = idx >> 5;   // 0..63
            int c = idx & 31;   // 0..31
            As[c][r] = g_xn[(i0 + r) * D + kc + c];
            Bs[c][r] = g_xn[(j0 + r) * D + kc + c];
        }
        __syncthreads();
        #pragma unroll
        for (int kk = 0; kk < KC; ++kk) {
            float a[4], b[4];
            #pragma unroll
            for (int i = 0; i < 4; ++i) a[i] = As[kk][cy * 4 + i];
            #pragma unroll
            for (int j = 0; j < 4; ++j) b[j] = Bs[kk][cx * 4 + j];
            #pragma unroll
            for (int i = 0; i < 4; ++i)
                #pragma unroll
                for (int j = 0; j < 4; ++j)
                    acc[i][j] = fmaf(a[i], b[j], acc[i][j]);
        }
    }

    // epilogue: exp, mask (skip i==j residue), row & col partial sums
    float rs[4] = {0.f, 0.f, 0.f, 0.f};
    float cs[4] = {0.f, 0.f, 0.f, 0.f};
    #pragma unroll
    for (int i = 0; i < 4; ++i) {
        #pragma unroll
        for (int j = 0; j < 4; ++j) {
            if (i != j) {
                float v = expf(acc[i][j] * TINV);
                rs[i] += v;
                cs[j] += v;
            }
        }
    }

    // row sums: reduce across the 16 cx lanes (xor 8..1 stays in 16-lane half)
    #pragma unroll
    for (int s = 8; s >= 1; s >>= 1) {
        #pragma unroll
        for (int i = 0; i < 4; ++i)
            rs[i] += __shfl_xor_sync(0xffffffffu, rs[i], s);
    }
    if (cx == 0) {
        #pragma unroll
        for (int i = 0; i < 4; ++i)
            atomicAdd(&g_den[i0 + cy * 4 + i], rs[i]);
    }

    if (bi != bj) {
        // col sums: combine the two cy's in this warp, then shared-atomic across warps
        #pragma unroll
        for (int j = 0; j < 4; ++j)
            cs[j] += __shfl_xor_sync(0xffffffffu, cs[j], 16);
        if ((tid & 31) < 16) {
            #pragma unroll
            for (int j = 0; j < 4; ++j)
                atomicAdd(&colred[cx * 4 + j], cs[j]);
        }
        __syncthreads();
        if (tid < TILE)
            atomicAdd(&g_den[j0 + tid], colred[tid]);
    }
}

// ---------------------------------------------------------------------------
// Kernel 4: final loss reduction (single block => deterministic tree)
// ---------------------------------------------------------------------------
__global__ __launch_bounds__(256) void k_finalize(float* __restrict__ out) {
    const int tid = threadIdx.x;
    __shared__ float red[256];

    float local = 0.0f;
    for (int p = tid; p < BATCH; p += 256) {
        float d1 = g_den[p];
        float d2 = g_den[BATCH + p];
        float d3 = g_den[2 * BATCH + p];
        float n12 = g_num[p];
        float n13 = g_num[BATCH + p];
        float n23 = g_num[2 * BATCH + p];
        local += log1pf(d1 / n12) + log1pf(d2 / n12)
               + log1pf(d1 / n13) + log1pf(d3 / n13)
               + log1pf(d2 / n23) + log1pf(d3 / n23);
    }
    red[tid] = local;
    __syncthreads();
    for (int s = 128; s >= 1; s >>= 1) {
        if (tid < s) red[tid] += red[tid + s];
        __syncthreads();
    }
    if (tid == 0) out[0] = red[0] / (2.0f * (float)BATCH);
}

extern "C" void kernel_launch(void* const* d_in, const int* in_sizes, int n_in,
                              void* d_out, int out_size) {
    const float* reg_pred = (const float*)d_in[0];
    float* out = (float*)d_out;

    k_normalize<<<BS, 256>>>(reg_pred);
    k_numerators<<<BATCH, 96>>>();
    dim3 grid(NB, NB);
    k_den_gemm<<<grid, 256>>>();
    k_finalize<<<1, 256>>>(out);
}

// round 3
// speedup vs baseline: 4.2368x; 4.2368x over previous
#include <cuda_runtime.h>
#include <cuda_bf16.h>
#include <math.h>
#include <stdint.h>

#define BS    12288     // 3 * 4096
#define BATCH 4096
#define D     256
#define TINV  10.0f     // 1 / temp

// GEMM tiling
#define TM    128
#define TN    128
#define KC    32                 // k-chunk (bf16 elems)
#define NBX   (BS / TN)          // 96
#define NBY   (BS / TM)          // 96
#define ROWB  80                 // smem row stride in bytes (32 bf16 = 64B + 16B pad)
#define TILEB (128 * ROWB)       // 10240 bytes per staged tile

// Scratch (device globals; no allocation allowed)
__device__ float g_xn[BS * D];                       // normalized rows fp32 (numerators)
__device__ __align__(16) __nv_bfloat16 g_xb[BS * D]; // normalized rows bf16 (GEMM)
__device__ float g_den[BS];                          // masked row sums of exp
__device__ float g_num[3 * BATCH];                   // n12, n13, n23

__device__ __forceinline__ uint32_t smem_u32(const void* p) {
    uint32_t a;
    asm("{ .reg .u64 t; cvta.to.shared.u64 t, %1; cvt.u32.u64 %0, t; }" : "=r"(a) : "l"(p));
    return a;
}

// ---------------------------------------------------------------------------
// Kernel 1: row-normalize + bf16 copy + zero g_den
// ---------------------------------------------------------------------------
__global__ __launch_bounds__(256) void k_normalize(const float* __restrict__ x) {
    const int row = blockIdx.x;
    const int tid = threadIdx.x;
    __shared__ float red[8];

    float v = x[row * D + tid];
    float ss = v * v;
    #pragma unroll
    for (int s = 16; s >= 1; s >>= 1) ss += __shfl_xor_sync(0xffffffffu, ss, s);
    if ((tid & 31) == 0) red[tid >> 5] = ss;
    __syncthreads();
    if (tid < 32) {
        float t = (tid < 8) ? red[tid] : 0.0f;
        #pragma unroll
        for (int s = 4; s >= 1; s >>= 1) t += __shfl_xor_sync(0xffffffffu, t, s);
        if (tid == 0) red[0] = t;
    }
    __syncthreads();
    const float inv = 1.0f / fmaxf(sqrtf(red[0]), 1e-6f);
    const float xn = v * inv;
    g_xn[row * D + tid] = xn;
    g_xb[row * D + tid] = __float2bfloat16(xn);
    if (tid == 0) g_den[row] = 0.0f;
}

// ---------------------------------------------------------------------------
// Kernel 2: fp32 numerator dots; zero out[0]
// ---------------------------------------------------------------------------
__global__ __launch_bounds__(96) void k_numerators(float* __restrict__ out) {
    const int p    = blockIdx.x;
    const int w    = threadIdx.x >> 5;
    const int lane = threadIdx.x & 31;
    if (p == 0 && threadIdx.x == 0) out[0] = 0.0f;

    int ra, rb;
    if (w == 0)      { ra = p;         rb = BATCH + p;     }
    else if (w == 1) { ra = p;         rb = 2 * BATCH + p; }
    else             { ra = BATCH + p; rb = 2 * BATCH + p; }

    const float* a = g_xn + ra * D;
    const float* b = g_xn + rb * D;
    float dot = 0.0f;
    #pragma unroll
    for (int u = 0; u < D / 32; ++u) {
        int idx = lane + 32 * u;
        dot = fmaf(a[idx], b[idx], dot);
    }
    #pragma unroll
    for (int s = 16; s >= 1; s >>= 1) dot += __shfl_xor_sync(0xffffffffu, dot, s);
    if (lane == 0) g_num[w * BATCH + p] = expf(dot * TINV);
}

// ---------------------------------------------------------------------------
// Kernel 3: mma.sync bf16 GEMM (128x128 tile) + exp + masked row sums.
// 8 warps: warp_m = wid>>2 (64 rows), warp_n = wid&3 (32 cols).
// Per warp: 4 m-frags x 4 n-frags of m16n8k16.
// Mask: exclude (col%4 == row%4); tile origins 4-aligned so per-lane
// residues are fixed: col%4 of c0 = 2*(lane&1), row%4 = (lane>>2)&3.
// ---------------------------------------------------------------------------
__global__ __launch_bounds__(256, 2) void k_den_gemm_mma() {
    __shared__ __align__(16) uint8_t sm[2][2][TILEB];   // [buf][A/B][tile]
    __shared__ float sden[TM];

    const int tid    = threadIdx.x;
    const int wid    = tid >> 5;
    const int lane   = tid & 31;
    const int warp_m = wid >> 2;      // 0..1
    const int warp_n = wid & 3;       // 0..3
    const int i0     = blockIdx.y * TM;
    const int j0     = blockIdx.x * TN;

    if (tid < TM) sden[tid] = 0.0f;

    // ---- cp.async staging: 1024 x 16B per chunk (A: 512, B: 512) ----
    auto stage = [&](int buf, int kc) {
        #pragma unroll
        for (int t = 0; t < 4; ++t) {
            int idx = tid + t * 256;            // 0..1023
            int mat = idx >> 9;                 // 0=A, 1=B
            int r   = (idx >> 2) & 127;
            int seg = idx & 3;                  // 16B segment (8 bf16)
            const __nv_bfloat16* g = g_xb
                + (size_t)((mat ? j0 : i0) + r) * D + kc + seg * 8;
            uint32_t s = smem_u32(&sm[buf][mat][r * ROWB + seg * 16]);
            asm volatile("cp.async.cg.shared.global [%0], [%1], 16;"
                         :: "r"(s), "l"(g));
        }
        asm volatile("cp.async.commit_group;" ::: "memory");
    };

    float acc[4][4][4];
    #pragma unroll
    for (int mf = 0; mf < 4; ++mf)
        #pragma unroll
        for (int nf = 0; nf < 4; ++nf)
            #pragma unroll
            for (int c = 0; c < 4; ++c) acc[mf][nf][c] = 0.0f;

    stage(0, 0);

    #pragma unroll
    for (int ch = 0; ch < D / KC; ++ch) {
        if (ch < D / KC - 1) {
            stage((ch + 1) & 1, (ch + 1) * KC);
            asm volatile("cp.async.wait_group 1;" ::: "memory");
        } else {
            asm volatile("cp.async.wait_group 0;" ::: "memory");
        }
        __syncthreads();

        const uint8_t* A = sm[ch & 1][0];
        const uint8_t* B = sm[ch & 1][1];

        #pragma unroll
        for (int ks = 0; ks < 2; ++ks) {        // two k16 steps per chunk
            uint32_t a[4][4], b[2][4];
            // A frags: lanes 0-15 -> rows 0-15 kseg0, lanes 16-31 -> rows 0-15 kseg1
            #pragma unroll
            for (int mf = 0; mf < 4; ++mf) {
                int row = warp_m * 64 + mf * 16 + (lane & 15);
                int seg = ks * 2 + (lane >> 4);
                uint32_t addr = smem_u32(A + row * ROWB + seg * 16);
                asm volatile("ldmatrix.sync.aligned.m8n8.x4.shared.b16 "
                             "{%0,%1,%2,%3}, [%4];"
                             : "=r"(a[mf][0]), "=r"(a[mf][1]),
                               "=r"(a[mf][2]), "=r"(a[mf][3])
                             : "r"(addr));
            }
            // B frags: each x4 covers two n-frags (8 cols each), both k-halves
            #pragma unroll
            for (int bh = 0; bh < 2; ++bh) {
                int n   = warp_n * 32 + bh * 16 + ((lane >> 4) << 3) + (lane & 7);
                int seg = ks * 2 + ((lane >> 3) & 1);
                uint32_t addr = smem_u32(B + n * ROWB + seg * 16);
                asm volatile("ldmatrix.sync.aligned.m8n8.x4.shared.b16 "
                             "{%0,%1,%2,%3}, [%4];"
                             : "=r"(b[bh][0]), "=r"(b[bh][1]),
                               "=r"(b[bh][2]), "=r"(b[bh][3])
                             : "r"(addr));
            }
            #pragma unroll
            for (int mf = 0; mf < 4; ++mf) {
                #pragma unroll
                for (int nf = 0; nf < 4; ++nf) {
                    uint32_t b0 = b[nf >> 1][(nf & 1) * 2 + 0];
                    uint32_t b1 = b[nf >> 1][(nf & 1) * 2 + 1];
                    asm volatile(
                        "mma.sync.aligned.m16n8k16.row.col.f32.bf16.bf16.f32 "
                        "{%0,%1,%2,%3}, {%4,%5,%6,%7}, {%8,%9}, {%0,%1,%2,%3};"
                        : "+f"(acc[mf][nf][0]), "+f"(acc[mf][nf][1]),
                          "+f"(acc[mf][nf][2]), "+f"(acc[mf][nf][3])
                        : "r"(a[mf][0]), "r"(a[mf][1]),
                          "r"(a[mf][2]), "r"(a[mf][3]),
                          "r"(b0), "r"(b1));
                }
            }
        }
        __syncthreads();
    }

    // ---- Epilogue: exp + masked row sums ----
    const int r4   = (lane >> 2) & 3;           // row % 4 (both c0/c1 row and +8 row)
    const bool inc0 = ((2 * (lane & 1))     != r4);  // c0/c2 columns
    const bool inc1 = ((2 * (lane & 1) + 1) != r4);  // c1/c3 columns

    #pragma unroll
    for (int mf = 0; mf < 4; ++mf) {
        float slo = 0.0f, shi = 0.0f;
        #pragma unroll
        for (int nf = 0; nf < 4; ++nf) {
            if (inc0) slo += __expf(acc[mf][nf][0] * TINV);
            if (inc1) slo += __expf(acc[mf][nf][1] * TINV);
            if (inc0) shi += __expf(acc[mf][nf][2] * TINV);
            if (inc1) shi += __expf(acc[mf][nf][3] * TINV);
        }
        // reduce across the 4 lanes of this row group (lane&3)
        #pragma unroll
        for (int s = 1; s <= 2; s <<= 1) {
            slo += __shfl_xor_sync(0xffffffffu, slo, s);
            shi += __shfl_xor_sync(0xffffffffu, shi, s);
        }
        if ((lane & 3) == 0) {
            int row = warp_m * 64 + mf * 16 + (lane >> 2);
            atomicAdd(&sden[row], slo);
            atomicAdd(&sden[row + 8], shi);
        }
    }
    __syncthreads();
    if (tid < TM) atomicAdd(&g_den[i0 + tid], sden[tid]);
}

// ---------------------------------------------------------------------------
// Kernel 4: final loss; 16 blocks, atomic partials into out[0]
// ---------------------------------------------------------------------------
__global__ __launch_bounds__(256) void k_finalize(float* __restrict__ out) {
    const int tid = threadIdx.x;
    const int p = blockIdx.x * 256 + tid;
    __shared__ float red[256];

    float d1 = g_den[p];
    float d2 = g_den[BATCH + p];
    float d3 = g_den[2 * BATCH + p];
    float n12 = g_num[p];
    float n13 = g_num[BATCH + p];
    float n23 = g_num[2 * BATCH + p];
    float local = log1pf(d1 / n12) + log1pf(d2 / n12)
                + log1pf(d1 / n13) + log1pf(d3 / n13)
                + log1pf(d2 / n23) + log1pf(d3 / n23);

    red[tid] = local;
    __syncthreads();
    for (int s = 128; s >= 1; s >>= 1) {
        if (tid < s) red[tid] += red[tid + s];
        __syncthreads();
    }
    if (tid == 0) atomicAdd(out, red[0] / (2.0f * (float)BATCH));
}

extern "C" void kernel_launch(void* const* d_in, const int* in_sizes, int n_in,
                              void* d_out, int out_size) {
    const float* reg_pred = (const float*)d_in[0];
    float* out = (float*)d_out;

    k_normalize<<<BS, 256>>>(reg_pred);
    k_numerators<<<BATCH, 96>>>(out);
    dim3 grid(NBX, NBY);
    k_den_gemm_mma<<<grid, 256>>>();
    k_finalize<<<BATCH / 256, 256>>>(out);
}

// round 4
// speedup vs baseline: 6.9065x; 1.6301x over previous
#include <cuda_runtime.h>
#include <cuda_bf16.h>
#include <math.h>
#include <stdint.h>

#define BS    12288     // 3 * 4096
#define BATCH 4096
#define D     256
#define TINV  10.0f     // 1 / temp

// GEMM tiling
#define TM    128
#define TN    128
#define KC    32                 // k-chunk (bf16 elems)
#define NB    (BS / TM)          // 96
#define NPAIR (NB * (NB + 1) / 2)  // 4656 upper-triangular tiles
#define ROWB  80                 // smem row stride in bytes (32 bf16 = 64B + 16B pad)
#define TILEB (128 * ROWB)       // 10240 bytes per staged tile

// Scratch (device globals; no allocation allowed)
__device__ float g_xn[BS * D];                       // normalized rows fp32 (numerators)
__device__ __align__(16) __nv_bfloat16 g_xb[BS * D]; // normalized rows bf16 (GEMM)
__device__ float g_den[BS];                          // masked row sums of exp
__device__ float g_num[3 * BATCH];                   // n12, n13, n23

__device__ __forceinline__ uint32_t smem_u32(const void* p) {
    uint32_t a;
    asm("{ .reg .u64 t; cvta.to.shared.u64 t, %1; cvt.u32.u64 %0, t; }" : "=r"(a) : "l"(p));
    return a;
}

// ---------------------------------------------------------------------------
// Kernel 1: row-normalize + bf16 copy + zero g_den
// ---------------------------------------------------------------------------
__global__ __launch_bounds__(256) void k_normalize(const float* __restrict__ x) {
    const int row = blockIdx.x;
    const int tid = threadIdx.x;
    __shared__ float red[8];

    float v = x[row * D + tid];
    float ss = v * v;
    #pragma unroll
    for (int s = 16; s >= 1; s >>= 1) ss += __shfl_xor_sync(0xffffffffu, ss, s);
    if ((tid & 31) == 0) red[tid >> 5] = ss;
    __syncthreads();
    if (tid < 32) {
        float t = (tid < 8) ? red[tid] : 0.0f;
        #pragma unroll
        for (int s = 4; s >= 1; s >>= 1) t += __shfl_xor_sync(0xffffffffu, t, s);
        if (tid == 0) red[0] = t;
    }
    __syncthreads();
    const float inv = 1.0f / fmaxf(sqrtf(red[0]), 1e-6f);
    const float xn = v * inv;
    g_xn[row * D + tid] = xn;
    g_xb[row * D + tid] = __float2bfloat16(xn);
    if (tid == 0) g_den[row] = 0.0f;
}

// ---------------------------------------------------------------------------
// Kernel 2: fp32 numerator dots; zero out[0]
// ---------------------------------------------------------------------------
__global__ __launch_bounds__(96) void k_numerators(float* __restrict__ out) {
    const int p    = blockIdx.x;
    const int w    = threadIdx.x >> 5;
    const int lane = threadIdx.x & 31;
    if (p == 0 && threadIdx.x == 0) out[0] = 0.0f;

    int ra, rb;
    if (w == 0)      { ra = p;         rb = BATCH + p;     }
    else if (w == 1) { ra = p;         rb = 2 * BATCH + p; }
    else             { ra = BATCH + p; rb = 2 * BATCH + p; }

    const float* a = g_xn + ra * D;
    const float* b = g_xn + rb * D;
    float dot = 0.0f;
    #pragma unroll
    for (int u = 0; u < D / 32; ++u) {
        int idx = lane + 32 * u;
        dot = fmaf(a[idx], b[idx], dot);
    }
    #pragma unroll
    for (int s = 16; s >= 1; s >>= 1) dot += __shfl_xor_sync(0xffffffffu, dot, s);
    if (lane == 0) g_num[w * BATCH + p] = expf(dot * TINV);
}

// ---------------------------------------------------------------------------
// Kernel 3: symmetric mma.sync bf16 GEMM over upper-triangular 128x128 tiles.
// Off-diagonal tiles contribute masked row sums to den[i-range] AND masked
// column sums to den[j-range]; diagonal tiles row sums only.
// C-fragment layout (m16n8): c0=(r, 2q) c1=(r, 2q+1) c2=(r+8, 2q) c3=(r+8, 2q+1)
// with r = lane>>2, q = lane&3.  Mask: exclude col%4 == row%4.
//   row%4 = (lane>>2)&3 (same for r and r+8); col%4 = 2*(lane&1) (+1 for c1/c3).
// ---------------------------------------------------------------------------
__global__ __launch_bounds__(256, 2) void k_den_gemm_mma() {
    __shared__ __align__(16) uint8_t sm[2][2][TILEB];   // [buf][A/B][tile]
    __shared__ float sden[TM];    // row sums
    __shared__ float sdenc[TN];   // col sums (off-diag only)

    const int tid    = threadIdx.x;
    const int wid    = tid >> 5;
    const int lane   = tid & 31;
    const int warp_m = wid >> 2;      // 0..1
    const int warp_n = wid & 3;       // 0..3

    // --- triangular decode: blockIdx.x -> (bi, bj) with bj >= bi ---
    int bi;
    {
        const int t = blockIdx.x;
        float disc = (NB + 0.5f) * (NB + 0.5f) - 2.0f * (float)t;
        bi = (int)((float)NB + 0.5f - sqrtf(disc));
        // fixup against base(bi) = bi*NB - bi*(bi-1)/2
        while (bi > 0 && t < bi * NB - bi * (bi - 1) / 2) --bi;
        while (t >= (bi + 1) * NB - (bi + 1) * bi / 2) ++bi;
    }
    const int base = bi * NB - bi * (bi - 1) / 2;
    const int bj   = bi + (blockIdx.x - base);
    const int i0   = bi * TM;
    const int j0   = bj * TN;
    const bool offdiag = (bi != bj);

    if (tid < TM) sden[tid] = 0.0f;
    if (tid < TN) sdenc[tid] = 0.0f;

    // ---- cp.async staging: 1024 x 16B per chunk (A: 512, B: 512) ----
    auto stage = [&](int buf, int kc) {
        #pragma unroll
        for (int t = 0; t < 4; ++t) {
            int idx = tid + t * 256;            // 0..1023
            int mat = idx >> 9;                 // 0=A, 1=B
            int r   = (idx >> 2) & 127;
            int seg = idx & 3;                  // 16B segment (8 bf16)
            const __nv_bfloat16* g = g_xb
                + (size_t)((mat ? j0 : i0) + r) * D + kc + seg * 8;
            uint32_t s = smem_u32(&sm[buf][mat][r * ROWB + seg * 16]);
            asm volatile("cp.async.cg.shared.global [%0], [%1], 16;"
                         :: "r"(s), "l"(g));
        }
        asm volatile("cp.async.commit_group;" ::: "memory");
    };

    float acc[4][4][4];
    #pragma unroll
    for (int mf = 0; mf < 4; ++mf)
        #pragma unroll
        for (int nf = 0; nf < 4; ++nf)
            #pragma unroll
            for (int c = 0; c < 4; ++c) acc[mf][nf][c] = 0.0f;

    stage(0, 0);

    #pragma unroll
    for (int ch = 0; ch < D / KC; ++ch) {
        if (ch < D / KC - 1) {
            stage((ch + 1) & 1, (ch + 1) * KC);
            asm volatile("cp.async.wait_group 1;" ::: "memory");
        } else {
            asm volatile("cp.async.wait_group 0;" ::: "memory");
        }
        __syncthreads();

        const uint8_t* A = sm[ch & 1][0];
        const uint8_t* B = sm[ch & 1][1];

        #pragma unroll
        for (int ks = 0; ks < 2; ++ks) {        // two k16 steps per chunk
            uint32_t a[4][4], b[2][4];
            #pragma unroll
            for (int mf = 0; mf < 4; ++mf) {
                int row = warp_m * 64 + mf * 16 + (lane & 15);
                int seg = ks * 2 + (lane >> 4);
                uint32_t addr = smem_u32(A + row * ROWB + seg * 16);
                asm volatile("ldmatrix.sync.aligned.m8n8.x4.shared.b16 "
                             "{%0,%1,%2,%3}, [%4];"
                             : "=r"(a[mf][0]), "=r"(a[mf][1]),
                               "=r"(a[mf][2]), "=r"(a[mf][3])
                             : "r"(addr));
            }
            #pragma unroll
            for (int bh = 0; bh < 2; ++bh) {
                int n   = warp_n * 32 + bh * 16 + ((lane >> 4) << 3) + (lane & 7);
                int seg = ks * 2 + ((lane >> 3) & 1);
                uint32_t addr = smem_u32(B + n * ROWB + seg * 16);
                asm volatile("ldmatrix.sync.aligned.m8n8.x4.shared.b16 "
                             "{%0,%1,%2,%3}, [%4];"
                             : "=r"(b[bh][0]), "=r"(b[bh][1]),
                               "=r"(b[bh][2]), "=r"(b[bh][3])
                             : "r"(addr));
            }
            #pragma unroll
            for (int mf = 0; mf < 4; ++mf) {
                #pragma unroll
                for (int nf = 0; nf < 4; ++nf) {
                    uint32_t b0 = b[nf >> 1][(nf & 1) * 2 + 0];
                    uint32_t b1 = b[nf >> 1][(nf & 1) * 2 + 1];
                    asm volatile(
                        "mma.sync.aligned.m16n8k16.row.col.f32.bf16.bf16.f32 "
                        "{%0,%1,%2,%3}, {%4,%5,%6,%7}, {%8,%9}, {%0,%1,%2,%3};"
                        : "+f"(acc[mf][nf][0]), "+f"(acc[mf][nf][1]),
                          "+f"(acc[mf][nf][2]), "+f"(acc[mf][nf][3])
                        : "r"(a[mf][0]), "r"(a[mf][1]),
                          "r"(a[mf][2]), "r"(a[mf][3]),
                          "r"(b0), "r"(b1));
                }
            }
        }
        __syncthreads();
    }

    // ---- Epilogue: exp once, accumulate row sums (+ col sums if off-diag) ----
    const int r4    = (lane >> 2) & 3;                 // row % 4
    const bool inc0 = ((2 * (lane & 1))     != r4);    // even cols (c0/c2)
    const bool inc1 = ((2 * (lane & 1) + 1) != r4);    // odd  cols (c1/c3)

    float cs[4][2];                                    // col sums per nf (col pair)
    #pragma unroll
    for (int nf = 0; nf < 4; ++nf) { cs[nf][0] = 0.0f; cs[nf][1] = 0.0f; }

    #pragma unroll
    for (int mf = 0; mf < 4; ++mf) {
        float slo = 0.0f, shi = 0.0f;
        #pragma unroll
        for (int nf = 0; nf < 4; ++nf) {
            float e0 = inc0 ? __expf(acc[mf][nf][0] * TINV) : 0.0f;
            float e1 = inc1 ? __expf(acc[mf][nf][1] * TINV) : 0.0f;
            float e2 = inc0 ? __expf(acc[mf][nf][2] * TINV) : 0.0f;
            float e3 = inc1 ? __expf(acc[mf][nf][3] * TINV) : 0.0f;
            slo += e0 + e1;
            shi += e2 + e3;
            cs[nf][0] += e0 + e2;
            cs[nf][1] += e1 + e3;
        }
        // row-sum reduce across the 4 lanes of this row group (lane&3)
        #pragma unroll
        for (int s = 1; s <= 2; s <<= 1) {
            slo += __shfl_xor_sync(0xffffffffu, slo, s);
            shi += __shfl_xor_sync(0xffffffffu, shi, s);
        }
        if ((lane & 3) == 0) {
            int row = warp_m * 64 + mf * 16 + (lane >> 2);
            atomicAdd(&sden[row], slo);
            atomicAdd(&sden[row + 8], shi);
        }
    }

    if (offdiag) {
        // col-sum reduce over rows (lane>>2 axis): xor 4, 8, 16
        #pragma unroll
        for (int nf = 0; nf < 4; ++nf) {
            #pragma unroll
            for (int s = 4; s <= 16; s <<= 1) {
                cs[nf][0] += __shfl_xor_sync(0xffffffffu, cs[nf][0], s);
                cs[nf][1] += __shfl_xor_sync(0xffffffffu, cs[nf][1], s);
            }
        }
        if (lane < 4) {
            #pragma unroll
            for (int nf = 0; nf < 4; ++nf) {
                int col = warp_n * 32 + nf * 8 + 2 * lane;
                atomicAdd(&sdenc[col],     cs[nf][0]);
                atomicAdd(&sdenc[col + 1], cs[nf][1]);
            }
        }
    }

    __syncthreads();
    if (tid < TM) atomicAdd(&g_den[i0 + tid], sden[tid]);
    if (offdiag && tid < TN) atomicAdd(&g_den[j0 + tid], sdenc[tid]);
}

// ---------------------------------------------------------------------------
// Kernel 4: final loss; 16 blocks, atomic partials into out[0]
// ---------------------------------------------------------------------------
__global__ __launch_bounds__(256) void k_finalize(float* __restrict__ out) {
    const int tid = threadIdx.x;
    const int p = blockIdx.x * 256 + tid;
    __shared__ float red[256];

    float d1 = g_den[p];
    float d2 = g_den[BATCH + p];
    float d3 = g_den[2 * BATCH + p];
    float n12 = g_num[p];
    float n13 = g_num[BATCH + p];
    float n23 = g_num[2 * BATCH + p];
    float local = log1pf(d1 / n12) + log1pf(d2 / n12)
                + log1pf(d1 / n13) + log1pf(d3 / n13)
                + log1pf(d2 / n23) + log1pf(d3 / n23);

    red[tid] = local;
    __syncthreads();
    for (int s = 128; s >= 1; s >>= 1) {
        if (tid < s) red[tid] += red[tid + s];
        __syncthreads();
    }
    if (tid == 0) atomicAdd(out, red[0] / (2.0f * (float)BATCH));
}

extern "C" void kernel_launch(void* const* d_in, const int* in_sizes, int n_in,
                              void* d_out, int out_size) {
    const float* reg_pred = (const float*)d_in[0];
    float* out = (float*)d_out;

    k_normalize<<<BS, 256>>>(reg_pred);
    k_numerators<<<BATCH, 96>>>(out);
    k_den_gemm_mma<<<NPAIR, 256>>>();
    k_finalize<<<BATCH / 256, 256>>>(out);
}